// round 8
// baseline (speedup 1.0000x reference)
#include <cuda_runtime.h>

#define FDIM 64
#define RDIM 4
#define F4   16
#define N_MAX   100000
#define E_MAX   100000
#define NNZ_MAX 800000
#define SCAN_B  1024

// Device-global scratch (no allocations allowed).
__device__ float  g_he[(size_t)E_MAX * FDIM];             // 25.6 MB
__device__ float4 g_msk[E_MAX];                           // per-edge rank masks (m0,m1,m2,-)
__device__ int    g_cnt[N_MAX + E_MAX];
__device__ int    g_fill[N_MAX + E_MAX];                  // cursors (init = g_ptr)
__device__ int    g_ptr[N_MAX + E_MAX + 1];
__device__ int    g_bsum[(N_MAX + E_MAX) / SCAN_B + 2];
__device__ int    g_tgt[2 * NNZ_MAX];                     // CSR: col ids; CSC: row ids
__device__ float  g_w[2 * NNZ_MAX];                       // per-entry vals

// ---- build --------------------------------------------------------------

__global__ void zero_kernel(int total) {
    int i = blockIdx.x * blockDim.x + threadIdx.x;
    if (i < total) g_cnt[i] = 0;
}

__global__ void hist_kernel(const int* __restrict__ rows,
                            const int* __restrict__ cols, int nnz, int N) {
    int i = blockIdx.x * blockDim.x + threadIdx.x;
    if (i >= nnz) return;
    atomicAdd(&g_cnt[rows[i]], 1);
    atomicAdd(&g_cnt[N + cols[i]], 1);
}

__global__ void scan1_kernel(int n) {
    __shared__ int sh[SCAN_B];
    int i = blockIdx.x * SCAN_B + threadIdx.x;
    int v = (i < n) ? g_cnt[i] : 0;
    sh[threadIdx.x] = v;
    __syncthreads();
    for (int off = 1; off < SCAN_B; off <<= 1) {
        int t = (threadIdx.x >= off) ? sh[threadIdx.x - off] : 0;
        __syncthreads();
        sh[threadIdx.x] += t;
        __syncthreads();
    }
    if (i < n) g_ptr[i] = sh[threadIdx.x] - v;
    if (threadIdx.x == SCAN_B - 1) g_bsum[blockIdx.x] = sh[threadIdx.x];
}

// 256 threads, warp-shuffle scan over nb (<256) block sums.
__global__ void scan2_kernel(int nb) {
    __shared__ int wsum[8];
    int i = threadIdx.x;
    int lane = i & 31, w = i >> 5;
    int v = (i < nb) ? g_bsum[i] : 0;
    int s = v;
    #pragma unroll
    for (int off = 1; off < 32; off <<= 1) {
        int t = __shfl_up_sync(0xFFFFFFFFu, s, off);
        if (lane >= off) s += t;
    }
    if (lane == 31) wsum[w] = s;
    __syncthreads();
    if (i == 0) {
        int acc = 0;
        #pragma unroll
        for (int j = 0; j < 8; j++) { int t = wsum[j]; wsum[j] = acc; acc += t; }
    }
    __syncthreads();
    if (i < nb) g_bsum[i] = s - v + wsum[w];              // exclusive
}

__global__ void scan3_kernel(int n, int nnz2) {
    int i = blockIdx.x * blockDim.x + threadIdx.x;
    if (i < n) {
        int p = g_ptr[i] + g_bsum[i / SCAN_B];
        g_ptr[i] = p;
        g_fill[i] = p;
    }
    if (i == 0) g_ptr[n] = nnz2;
}

__global__ void place_kernel(const int* __restrict__ rows,
                             const int* __restrict__ cols,
                             const float* __restrict__ vals,
                             int nnz, int N) {
    int i = blockIdx.x * blockDim.x + threadIdx.x;
    if (i >= nnz) return;
    int r = rows[i];
    int c = cols[i];
    float v = vals[i];
    int p1 = atomicAdd(&g_fill[r], 1);
    g_tgt[p1] = c;  g_w[p1] = v;                           // CSR entry: target edge
    int p2 = atomicAdd(&g_fill[N + c], 1);
    g_tgt[p2] = r;  g_w[p2] = v;                           // CSC entry: source node
}

__global__ void msk_kernel(const float* __restrict__ rank_masks,
                           const int* __restrict__ he_idxs, int E) {
    int e = blockIdx.x * blockDim.x + threadIdx.x;
    if (e >= E) return;
    int he = he_idxs[e];
    float4 m;
    m.x = rank_masks[he];
    m.y = rank_masks[E + he];
    m.z = rank_masks[2 * E + he];
    m.w = 0.f;
    g_msk[e] = m;
}

// ---- phase A: he[e][:] = sum_k w * x[src][:]  (one random hop, MLP=4) ---

__global__ void he_gather_kernel(const float* __restrict__ x, int E, int N) {
    int idx = blockIdx.x * blockDim.x + threadIdx.x;
    int e = idx >> 4;
    int t = idx & 15;
    if (e >= E) return;
    int beg = g_ptr[N + e];
    int end = g_ptr[N + e + 1];
    const float4* x4 = reinterpret_cast<const float4*>(x);
    float4 acc = make_float4(0.f, 0.f, 0.f, 0.f);
    int k = beg;
    for (; k + 4 <= end; k += 4) {
        int   r0 = g_tgt[k],   r1 = g_tgt[k+1], r2 = g_tgt[k+2], r3 = g_tgt[k+3];
        float w0 = g_w[k],     w1 = g_w[k+1],   w2 = g_w[k+2],   w3 = g_w[k+3];
        float4 v0 = x4[r0 * F4 + t];
        float4 v1 = x4[r1 * F4 + t];
        float4 v2 = x4[r2 * F4 + t];
        float4 v3 = x4[r3 * F4 + t];
        acc.x += w0*v0.x + w1*v1.x + w2*v2.x + w3*v3.x;
        acc.y += w0*v0.y + w1*v1.y + w2*v2.y + w3*v3.y;
        acc.z += w0*v0.z + w1*v1.z + w2*v2.z + w3*v3.z;
        acc.w += w0*v0.w + w1*v1.w + w2*v2.w + w3*v3.w;
    }
    for (; k < end; k++) {
        int r = g_tgt[k];
        float w = g_w[k];
        float4 v = x4[r * F4 + t];
        acc.x += w*v.x; acc.y += w*v.y; acc.z += w*v.z; acc.w += w*v.w;
    }
    reinterpret_cast<float4*>(g_he)[(size_t)e * F4 + t] = acc;
}

// ---- phase B: out[n][r][:] = sum_k w * msk[c].r * he[c][:]; rank3 = x ---

__global__ void out_gather_kernel(const float* __restrict__ x,
                                  float* __restrict__ out, int N) {
    int idx = blockIdx.x * blockDim.x + threadIdx.x;
    int n = idx >> 4;
    int t = idx & 15;
    if (n >= N) return;
    int beg = g_ptr[n];
    int end = g_ptr[n + 1];
    const float4* he4 = reinterpret_cast<const float4*>(g_he);
    float4 a0 = make_float4(0.f, 0.f, 0.f, 0.f);
    float4 a1 = a0, a2 = a0;
    int k = beg;
    for (; k + 4 <= end; k += 4) {
        int   c0 = g_tgt[k],   c1 = g_tgt[k+1], c2 = g_tgt[k+2], c3 = g_tgt[k+3];
        float w0 = g_w[k],     w1 = g_w[k+1],   w2 = g_w[k+2],   w3 = g_w[k+3];
        float4 m0 = g_msk[c0], m1 = g_msk[c1], m2 = g_msk[c2], m3 = g_msk[c3];
        float4 h0 = he4[(size_t)c0 * F4 + t];
        float4 h1 = he4[(size_t)c1 * F4 + t];
        float4 h2 = he4[(size_t)c2 * F4 + t];
        float4 h3 = he4[(size_t)c3 * F4 + t];
        float s;
        s = w0*m0.x; a0.x += s*h0.x; a0.y += s*h0.y; a0.z += s*h0.z; a0.w += s*h0.w;
        s = w0*m0.y; a1.x += s*h0.x; a1.y += s*h0.y; a1.z += s*h0.z; a1.w += s*h0.w;
        s = w0*m0.z; a2.x += s*h0.x; a2.y += s*h0.y; a2.z += s*h0.z; a2.w += s*h0.w;
        s = w1*m1.x; a0.x += s*h1.x; a0.y += s*h1.y; a0.z += s*h1.z; a0.w += s*h1.w;
        s = w1*m1.y; a1.x += s*h1.x; a1.y += s*h1.y; a1.z += s*h1.z; a1.w += s*h1.w;
        s = w1*m1.z; a2.x += s*h1.x; a2.y += s*h1.y; a2.z += s*h1.z; a2.w += s*h1.w;
        s = w2*m2.x; a0.x += s*h2.x; a0.y += s*h2.y; a0.z += s*h2.z; a0.w += s*h2.w;
        s = w2*m2.y; a1.x += s*h2.x; a1.y += s*h2.y; a1.z += s*h2.z; a1.w += s*h2.w;
        s = w2*m2.z; a2.x += s*h2.x; a2.y += s*h2.y; a2.z += s*h2.z; a2.w += s*h2.w;
        s = w3*m3.x; a0.x += s*h3.x; a0.y += s*h3.y; a0.z += s*h3.z; a0.w += s*h3.w;
        s = w3*m3.y; a1.x += s*h3.x; a1.y += s*h3.y; a1.z += s*h3.z; a1.w += s*h3.w;
        s = w3*m3.z; a2.x += s*h3.x; a2.y += s*h3.y; a2.z += s*h3.z; a2.w += s*h3.w;
    }
    for (; k < end; k++) {
        int c = g_tgt[k];
        float w = g_w[k];
        float4 m = g_msk[c];
        float4 h = he4[(size_t)c * F4 + t];
        float s;
        s = w*m.x; a0.x += s*h.x; a0.y += s*h.y; a0.z += s*h.z; a0.w += s*h.w;
        s = w*m.y; a1.x += s*h.x; a1.y += s*h.y; a1.z += s*h.z; a1.w += s*h.w;
        s = w*m.z; a2.x += s*h.x; a2.y += s*h.y; a2.z += s*h.z; a2.w += s*h.w;
    }
    float4* out4 = reinterpret_cast<float4*>(out);
    size_t base = (size_t)n * (RDIM * F4);
    out4[base + 0 * F4 + t] = a0;
    out4[base + 1 * F4 + t] = a1;
    out4[base + 2 * F4 + t] = a2;
    out4[base + 3 * F4 + t] = reinterpret_cast<const float4*>(x)[n * F4 + t];
}

// ---- launch -------------------------------------------------------------

extern "C" void kernel_launch(void* const* d_in, const int* in_sizes, int n_in,
                              void* d_out, int out_size) {
    const float* x          = (const float*)d_in[0];
    const float* rank_masks = (const float*)d_in[1];
    const float* vals       = (const float*)d_in[2];
    const int*   he_idxs    = (const int*)d_in[3];
    const int*   rows       = (const int*)d_in[4];
    const int*   cols       = (const int*)d_in[5];
    float* out = (float*)d_out;

    int nnz = in_sizes[2];
    int E   = in_sizes[3];
    int N   = in_sizes[0] / FDIM;
    int total = N + E;
    int nb = (total + SCAN_B - 1) / SCAN_B;

    zero_kernel<<<(total + 255) / 256, 256>>>(total);
    hist_kernel<<<(nnz + 255) / 256, 256>>>(rows, cols, nnz, N);
    scan1_kernel<<<nb, SCAN_B>>>(total);
    scan2_kernel<<<1, 256>>>(nb);
    scan3_kernel<<<(total + 255) / 256, 256>>>(total, 2 * nnz);
    place_kernel<<<(nnz + 255) / 256, 256>>>(rows, cols, vals, nnz, N);
    msk_kernel<<<(E + 255) / 256, 256>>>(rank_masks, he_idxs, E);

    {
        long long th = (long long)E * 16;
        he_gather_kernel<<<(int)((th + 255) / 256), 256>>>(x, E, N);
    }
    {
        long long th = (long long)N * 16;
        out_gather_kernel<<<(int)((th + 255) / 256), 256>>>(x, out, N);
    }
}